// round 1
// baseline (speedup 1.0000x reference)
#include <cuda_runtime.h>
#include <cuda_bf16.h>

#define NUM_NODES 10000
#define N_EDGES   640000
#define D         128

// ---------------- device scratch (no allocations allowed) ----------------
__device__ float d_S[NUM_NODES * D];        // sum of x[src] per dst node
__device__ float d_A[NUM_NODES * D];        // sum of edge_attr per dst node
__device__ int   d_deg[NUM_NODES];
__device__ int   d_off[NUM_NODES + 1];
__device__ int   d_cur[NUM_NODES];
__device__ float d_degf[NUM_NODES];
__device__ int   d_perm[N_EDGES];
__device__ float d_Mf[512 * D];             // fused [W1a@W2a ; W1c@W2a ; W2b ; W1b@W2a]
__device__ float d_cvec[D];                 // b1 @ W2a
__device__ int   d_is64;

// ---------------- helpers ----------------
__device__ __forceinline__ int load_idx(const void* ei, int which, int e, int is64) {
    if (is64) {
        const long long* p = (const long long*)ei;
        return (int)__ldg(p + (size_t)which * N_EDGES + e);
    } else {
        const int* p = (const int*)ei;
        return __ldg(p + (size_t)which * N_EDGES + e);
    }
}

__device__ __forceinline__ float4 ldg4(const float* p) {
    return __ldg((const float4*)p);
}

// ---------------- K0: detect int64 vs int32 edge_index ----------------
// If int64 (values in [0,10000)), every high 32-bit word is zero.
// Probe odd int32 words of the first 1024 entries (safe: < 1.28M words either way).
__global__ void k_detect(const int* ei_words) {
    __shared__ int any;
    if (threadIdx.x == 0) any = 0;
    __syncthreads();
    int w = ei_words[2 * threadIdx.x + 1];
    if (w != 0) any = 1;   // racy benign
    __syncthreads();
    if (threadIdx.x == 0) d_is64 = (any == 0) ? 1 : 0;
}

// ---------------- K1: zero accumulators ----------------
__global__ void k_zero() {
    int stride = gridDim.x * blockDim.x;
    int tid = blockIdx.x * blockDim.x + threadIdx.x;
    for (int i = tid; i < NUM_NODES * D; i += stride) { d_S[i] = 0.f; d_A[i] = 0.f; }
    for (int i = tid; i < NUM_NODES; i += stride)     { d_deg[i] = 0; }
}

// ---------------- K2: fuse weight matrices ----------------
// Mf row layout (512 x 128):
//   [0,128):   M1  = W1[0:128]   @ W2[0:128]     (multiplies S)
//   [128,256): M3  = W1[256:384] @ W2[0:128]     (multiplies A)
//   [256,384): W2b = W2[128:256]                 (multiplies x)
//   [384,512): M2  = W1[128:256] @ W2[0:128]     (multiplies deg*x)
// cvec = b1 @ W2[0:128]
__global__ void k_fuse(const float* __restrict__ W1,
                       const float* __restrict__ b1,
                       const float* __restrict__ W2) {
    __shared__ float row[D];
    int r = blockIdx.x;     // 0..511
    int o = threadIdx.x;    // 0..127
    if (r >= 256 && r < 384) {
        d_Mf[r * D + o] = W2[(128 + (r - 256)) * D + o];
        return;
    }
    int w1row = (r < 128) ? r : (r < 256) ? (256 + (r - 128)) : (128 + (r - 384));
    row[o] = W1[w1row * D + o];
    __syncthreads();
    float acc = 0.f;
#pragma unroll 8
    for (int h = 0; h < D; h++) acc += row[h] * __ldg(W2 + h * D + o);
    d_Mf[r * D + o] = acc;

    if (r == 0) {
        __syncthreads();
        row[o] = b1[o];
        __syncthreads();
        float c = 0.f;
#pragma unroll 8
        for (int h = 0; h < D; h++) c += row[h] * __ldg(W2 + h * D + o);
        d_cvec[o] = c;
    }
}

// ---------------- K3: degree count ----------------
__global__ void k_deg(const void* ei) {
    int is64 = d_is64;
    int e = blockIdx.x * blockDim.x + threadIdx.x;
    if (e >= N_EDGES) return;
    int dst = load_idx(ei, 1, e, is64);
    atomicAdd(&d_deg[dst], 1);
}

// ---------------- K4: exclusive scan over degrees (single block) ----------------
__global__ void k_scan() {
    __shared__ int s[1024];
    int t = threadIdx.x;
    int base = t * 10;                 // 1024*10 >= 10000
    int degs[10];
    int loc = 0;
#pragma unroll
    for (int i = 0; i < 10; i++) {
        int n = base + i;
        degs[i] = (n < NUM_NODES) ? d_deg[n] : 0;
        loc += degs[i];
    }
    s[t] = loc;
    __syncthreads();
    for (int d = 1; d < 1024; d <<= 1) {
        int v = (t >= d) ? s[t - d] : 0;
        __syncthreads();
        s[t] += v;
        __syncthreads();
    }
    int run = s[t] - loc;              // exclusive prefix
#pragma unroll
    for (int i = 0; i < 10; i++) {
        int n = base + i;
        if (n < NUM_NODES) {
            d_off[n]  = run;
            d_cur[n]  = run;
            d_degf[n] = (float)degs[i];
            run += degs[i];
        }
    }
    if (t == 1023) d_off[NUM_NODES] = s[1023];
}

// ---------------- K5: scatter edge ids into CSR buckets ----------------
__global__ void k_scatter(const void* ei) {
    int is64 = d_is64;
    int e = blockIdx.x * blockDim.x + threadIdx.x;
    if (e >= N_EDGES) return;
    int dst = load_idx(ei, 1, e, is64);
    int pos = atomicAdd(&d_cur[dst], 1);
    d_perm[pos] = e;
}

// ---------------- K6: atomic-free segment sums (warp per node) ----------------
__global__ void k_agg(const float* __restrict__ x,
                      const float* __restrict__ ea,
                      const void* ei) {
    int is64 = d_is64;
    int n = blockIdx.x * 8 + (threadIdx.x >> 5);
    if (n >= NUM_NODES) return;
    int lane = threadIdx.x & 31;
    int j0 = d_off[n], j1 = d_off[n + 1];

    float4 aS = make_float4(0.f, 0.f, 0.f, 0.f);
    float4 aA = make_float4(0.f, 0.f, 0.f, 0.f);

    int j = j0;
    // unroll-4: break the perm->src->data dependent chain with independent loads
    for (; j + 4 <= j1; j += 4) {
        int e0 = __ldg(d_perm + j + 0);
        int e1 = __ldg(d_perm + j + 1);
        int e2 = __ldg(d_perm + j + 2);
        int e3 = __ldg(d_perm + j + 3);
        int s0 = load_idx(ei, 0, e0, is64);
        int s1 = load_idx(ei, 0, e1, is64);
        int s2 = load_idx(ei, 0, e2, is64);
        int s3 = load_idx(ei, 0, e3, is64);
        float4 x0 = ldg4(x + (size_t)s0 * D + lane * 4);
        float4 x1 = ldg4(x + (size_t)s1 * D + lane * 4);
        float4 x2 = ldg4(x + (size_t)s2 * D + lane * 4);
        float4 x3 = ldg4(x + (size_t)s3 * D + lane * 4);
        float4 a0 = ldg4(ea + (size_t)e0 * D + lane * 4);
        float4 a1 = ldg4(ea + (size_t)e1 * D + lane * 4);
        float4 a2 = ldg4(ea + (size_t)e2 * D + lane * 4);
        float4 a3 = ldg4(ea + (size_t)e3 * D + lane * 4);
        aS.x += (x0.x + x1.x) + (x2.x + x3.x);
        aS.y += (x0.y + x1.y) + (x2.y + x3.y);
        aS.z += (x0.z + x1.z) + (x2.z + x3.z);
        aS.w += (x0.w + x1.w) + (x2.w + x3.w);
        aA.x += (a0.x + a1.x) + (a2.x + a3.x);
        aA.y += (a0.y + a1.y) + (a2.y + a3.y);
        aA.z += (a0.z + a1.z) + (a2.z + a3.z);
        aA.w += (a0.w + a1.w) + (a2.w + a3.w);
    }
    for (; j < j1; j++) {
        int e0 = __ldg(d_perm + j);
        int s0 = load_idx(ei, 0, e0, is64);
        float4 x0 = ldg4(x + (size_t)s0 * D + lane * 4);
        float4 a0 = ldg4(ea + (size_t)e0 * D + lane * 4);
        aS.x += x0.x; aS.y += x0.y; aS.z += x0.z; aS.w += x0.w;
        aA.x += a0.x; aA.y += a0.y; aA.z += a0.z; aA.w += a0.w;
    }
    *(float4*)(d_S + (size_t)n * D + lane * 4) = aS;
    *(float4*)(d_A + (size_t)n * D + lane * 4) = aA;
}

// ---------------- K7: fused node GEMM ----------------
// out[10000,128] = U[10000,512] @ Mf[512,128] + deg (x) cvec + b2
// U assembled on the fly: [S | A | x | deg*x]
// Tile: 64 nodes x 128 outs per block, 256 threads, 4x8 per thread, kc=32.
__global__ void k_gemm(const float* __restrict__ x,
                       const float* __restrict__ b2,
                       float* __restrict__ out) {
    __shared__ float Us[64 * 33];     // padded stride 33 -> conflict-free
    __shared__ float Ms[32 * 128];
    int t = threadIdx.x;              // 0..255
    int n0 = blockIdx.x * 64;
    int og = t & 15;                  // 16 output groups of 8
    int ng = t >> 4;                  // 16 node groups of 4

    float acc[4][8];
#pragma unroll
    for (int i = 0; i < 4; i++)
#pragma unroll
        for (int jj = 0; jj < 8; jj++) acc[i][jj] = 0.f;

    for (int k0 = 0; k0 < 512; k0 += 32) {
        int region = k0 >> 7;
        int kloc = k0 & 127;
        const float* base = (region == 0) ? d_S : (region == 1) ? d_A : x;

        // U tile: 64x32 = 2048 floats, 8 per thread
#pragma unroll
        for (int v = 0; v < 2; v++) {
            int id = t * 8 + v * 4;
            int r = id >> 5, c = id & 31;
            int n = n0 + r;
            float4 val = make_float4(0.f, 0.f, 0.f, 0.f);
            if (n < NUM_NODES) {
                val = ldg4(base + (size_t)n * D + kloc + c);
                if (region == 3) {
                    float dg = d_degf[n];
                    val.x *= dg; val.y *= dg; val.z *= dg; val.w *= dg;
                }
            }
            Us[r * 33 + c + 0] = val.x;
            Us[r * 33 + c + 1] = val.y;
            Us[r * 33 + c + 2] = val.z;
            Us[r * 33 + c + 3] = val.w;
        }
        // Mf tile: 32x128 = 4096 floats, 16 per thread
#pragma unroll
        for (int v = 0; v < 4; v++) {
            int id = t * 16 + v * 4;
            int r = id >> 7, c = id & 127;
            *(float4*)(Ms + r * 128 + c) = ldg4(d_Mf + (size_t)(k0 + r) * 128 + c);
        }
        __syncthreads();

#pragma unroll
        for (int kk = 0; kk < 32; kk++) {
            float u[4];
#pragma unroll
            for (int i = 0; i < 4; i++) u[i] = Us[(ng * 4 + i) * 33 + kk];
            float4 m0 = *(float4*)(Ms + kk * 128 + og * 8);
            float4 m1 = *(float4*)(Ms + kk * 128 + og * 8 + 4);
            float m[8] = {m0.x, m0.y, m0.z, m0.w, m1.x, m1.y, m1.z, m1.w};
#pragma unroll
            for (int i = 0; i < 4; i++)
#pragma unroll
                for (int jj = 0; jj < 8; jj++)
                    acc[i][jj] += u[i] * m[jj];
        }
        __syncthreads();
    }

    // epilogue: + deg*cvec + b2
#pragma unroll
    for (int i = 0; i < 4; i++) {
        int n = n0 + ng * 4 + i;
        if (n >= NUM_NODES) continue;
        float dg = d_degf[n];
        float o8[8];
#pragma unroll
        for (int jj = 0; jj < 8; jj++) {
            int o = og * 8 + jj;
            o8[jj] = acc[i][jj] + dg * d_cvec[o] + b2[o];
        }
        float4* outp = (float4*)(out + (size_t)n * D + og * 8);
        outp[0] = make_float4(o8[0], o8[1], o8[2], o8[3]);
        outp[1] = make_float4(o8[4], o8[5], o8[6], o8[7]);
    }
}

// ---------------- launch ----------------
extern "C" void kernel_launch(void* const* d_in, const int* in_sizes, int n_in,
                              void* d_out, int out_size) {
    const float* x  = (const float*)d_in[0];
    const void*  ei = d_in[1];
    const float* ea = (const float*)d_in[2];
    const float* W1 = (const float*)d_in[3];
    const float* b1 = (const float*)d_in[4];
    const float* W2 = (const float*)d_in[5];
    const float* b2 = (const float*)d_in[6];
    float* out = (float*)d_out;

    k_detect<<<1, 1024>>>((const int*)ei);
    k_zero<<<256, 256>>>();
    k_fuse<<<512, 128>>>(W1, b1, W2);
    k_deg<<<(N_EDGES + 255) / 256, 256>>>(ei);
    k_scan<<<1, 1024>>>();
    k_scatter<<<(N_EDGES + 255) / 256, 256>>>(ei);
    k_agg<<<(NUM_NODES + 7) / 8, 256>>>(x, ea, ei);
    k_gemm<<<(NUM_NODES + 63) / 64, 256>>>(x, b2, out);
}